// round 1
// baseline (speedup 1.0000x reference)
#include <cuda_runtime.h>
#include <math.h>

#define D_MODEL 768
#define NHEAD   12
#define HDIM    64
#define SEQ     4096

// Scratch (allocation-free rule: __device__ globals)
__device__ float g_qp[SEQ * D_MODEL];
__device__ float g_kp[SEQ * D_MODEL];
__device__ float g_vp[SEQ * D_MODEL];
__device__ float g_ctx[SEQ * D_MODEL];

// ---------------------------------------------------------------------------
// Generic GEMM: C[M,N] = X[M,K] @ W[N,K]^T + bias[N]
// Both X and W are K-contiguous (row-major), so loads are coalesced.
// Tiles: 64x64 output per CTA, BK=16, 256 threads, 4x4 micro-tile/thread.
// ---------------------------------------------------------------------------
__global__ __launch_bounds__(256) void gemm_bias_kernel(
    const float* __restrict__ X, const float* __restrict__ W,
    const float* __restrict__ bias, float* __restrict__ C,
    int M, int N, int K)
{
    __shared__ float As[16][65];   // [k][m]
    __shared__ float Bs[16][65];   // [k][n]

    const int m0 = blockIdx.y * 64;
    const int n0 = blockIdx.x * 64;
    const int t  = threadIdx.x;
    const int tx = t & 15;         // 0..15 -> n micro
    const int ty = t >> 4;         // 0..15 -> m micro

    const int lrow = t >> 2;       // 0..63, tile row for loading
    const int lk   = (t & 3) * 4;  // 0,4,8,12 within BK

    float acc[4][4] = {};

    for (int kk = 0; kk < K; kk += 16) {
        float4 xa = *(const float4*)(X + (size_t)(m0 + lrow) * K + kk + lk);
        float4 wb = *(const float4*)(W + (size_t)(n0 + lrow) * K + kk + lk);
        As[lk + 0][lrow] = xa.x; As[lk + 1][lrow] = xa.y;
        As[lk + 2][lrow] = xa.z; As[lk + 3][lrow] = xa.w;
        Bs[lk + 0][lrow] = wb.x; Bs[lk + 1][lrow] = wb.y;
        Bs[lk + 2][lrow] = wb.z; Bs[lk + 3][lrow] = wb.w;
        __syncthreads();

#pragma unroll
        for (int k = 0; k < 16; ++k) {
            float a[4], b[4];
#pragma unroll
            for (int i = 0; i < 4; ++i) a[i] = As[k][ty * 4 + i];
#pragma unroll
            for (int j = 0; j < 4; ++j) b[j] = Bs[k][tx * 4 + j];
#pragma unroll
            for (int i = 0; i < 4; ++i)
#pragma unroll
                for (int j = 0; j < 4; ++j)
                    acc[i][j] += a[i] * b[j];
        }
        __syncthreads();
    }

#pragma unroll
    for (int i = 0; i < 4; ++i) {
        float4 r;
        r.x = acc[i][0] + bias[n0 + tx * 4 + 0];
        r.y = acc[i][1] + bias[n0 + tx * 4 + 1];
        r.z = acc[i][2] + bias[n0 + tx * 4 + 2];
        r.w = acc[i][3] + bias[n0 + tx * 4 + 3];
        *(float4*)(C + (size_t)(m0 + ty * 4 + i) * N + n0 + tx * 4) = r;
    }
}

// ---------------------------------------------------------------------------
// Flash attention (fp32, online softmax).
// Grid: (SEQ/64, NHEAD). Block: 256 threads.
// Each CTA: 64 query rows of one head. Iterates 64-key tiles over S=4096.
// qp/kp/vp layout: [S, D_MODEL]; head h occupies columns [h*64, h*64+64).
// Output written directly in [S, D_MODEL] layout (merged-heads) to g_ctx.
// ---------------------------------------------------------------------------
__global__ __launch_bounds__(256) void flash_attn_kernel(
    const float* __restrict__ qp, const float* __restrict__ kp,
    const float* __restrict__ vp, float* __restrict__ ctx)
{
    extern __shared__ float sm[];
    float* Qs  = sm;               // 64*65
    float* Ks  = Qs + 64 * 65;     // 64*65  (reused for V)
    float* Ss  = Ks + 64 * 65;     // 64*65
    float* m_s = Ss + 64 * 65;     // 64
    float* l_s = m_s + 64;         // 64
    float* a_s = l_s + 64;         // 64

    const int h  = blockIdx.y;
    const int q0 = blockIdx.x * 64;
    const int t  = threadIdx.x;
    const int tx = t & 15;
    const int ty = t >> 4;
    const float scale = 0.125f;    // 1/sqrt(64)

    // Load Q tile [64 rows x 64 dims]
    for (int idx = t; idx < 64 * 16; idx += 256) {
        int row = idx >> 4;
        int c   = (idx & 15) * 4;
        float4 v = *(const float4*)(qp + (size_t)(q0 + row) * D_MODEL + h * HDIM + c);
        Qs[row * 65 + c + 0] = v.x; Qs[row * 65 + c + 1] = v.y;
        Qs[row * 65 + c + 2] = v.z; Qs[row * 65 + c + 3] = v.w;
    }
    if (t < 64) { m_s[t] = -1e30f; l_s[t] = 0.0f; }

    float o[4][4] = {};
    __syncthreads();

    for (int k0 = 0; k0 < SEQ; k0 += 64) {
        // --- load K tile: Ks[key][dim]
        for (int idx = t; idx < 64 * 16; idx += 256) {
            int row = idx >> 4;
            int c   = (idx & 15) * 4;
            float4 v = *(const float4*)(kp + (size_t)(k0 + row) * D_MODEL + h * HDIM + c);
            Ks[row * 65 + c + 0] = v.x; Ks[row * 65 + c + 1] = v.y;
            Ks[row * 65 + c + 2] = v.z; Ks[row * 65 + c + 3] = v.w;
        }
        __syncthreads();

        // --- S = scale * Q @ K^T   (64x64)
        float s[4][4] = {};
#pragma unroll 8
        for (int d = 0; d < 64; ++d) {
            float a[4], b[4];
#pragma unroll
            for (int i = 0; i < 4; ++i) a[i] = Qs[(ty * 4 + i) * 65 + d];
#pragma unroll
            for (int j = 0; j < 4; ++j) b[j] = Ks[(tx * 4 + j) * 65 + d];
#pragma unroll
            for (int i = 0; i < 4; ++i)
#pragma unroll
                for (int j = 0; j < 4; ++j)
                    s[i][j] += a[i] * b[j];
        }
#pragma unroll
        for (int i = 0; i < 4; ++i)
#pragma unroll
            for (int j = 0; j < 4; ++j)
                Ss[(ty * 4 + i) * 65 + tx * 4 + j] = s[i][j] * scale;
        __syncthreads();

        // --- load V tile into Ks buffer (K no longer needed)
        for (int idx = t; idx < 64 * 16; idx += 256) {
            int row = idx >> 4;
            int c   = (idx & 15) * 4;
            float4 v = *(const float4*)(vp + (size_t)(k0 + row) * D_MODEL + h * HDIM + c);
            Ks[row * 65 + c + 0] = v.x; Ks[row * 65 + c + 1] = v.y;
            Ks[row * 65 + c + 2] = v.z; Ks[row * 65 + c + 3] = v.w;
        }

        // --- online softmax: 4 threads per row, 16 elems each
        {
            int row = t >> 2;
            int qq  = t & 3;
            float* srow = Ss + row * 65 + qq * 16;
            float pm = -1e30f;
#pragma unroll
            for (int j = 0; j < 16; ++j) pm = fmaxf(pm, srow[j]);
            pm = fmaxf(pm, __shfl_xor_sync(0xffffffffu, pm, 1));
            pm = fmaxf(pm, __shfl_xor_sync(0xffffffffu, pm, 2));
            float mold = m_s[row];
            float mnew = fmaxf(mold, pm);
            float psum = 0.0f;
#pragma unroll
            for (int j = 0; j < 16; ++j) {
                float p = __expf(srow[j] - mnew);
                srow[j] = p;
                psum += p;
            }
            psum += __shfl_xor_sync(0xffffffffu, psum, 1);
            psum += __shfl_xor_sync(0xffffffffu, psum, 2);
            if (qq == 0) {
                float alpha = __expf(mold - mnew);
                l_s[row] = l_s[row] * alpha + psum;
                m_s[row] = mnew;
                a_s[row] = alpha;
            }
        }
        __syncthreads();

        // --- O = O*alpha + P @ V
        float al[4];
#pragma unroll
        for (int i = 0; i < 4; ++i) al[i] = a_s[ty * 4 + i];
#pragma unroll
        for (int i = 0; i < 4; ++i)
#pragma unroll
            for (int j = 0; j < 4; ++j)
                o[i][j] *= al[i];

#pragma unroll 8
        for (int k = 0; k < 64; ++k) {
            float p[4], v[4];
#pragma unroll
            for (int i = 0; i < 4; ++i) p[i] = Ss[(ty * 4 + i) * 65 + k];
#pragma unroll
            for (int j = 0; j < 4; ++j) v[j] = Ks[k * 65 + tx * 4 + j];
#pragma unroll
            for (int i = 0; i < 4; ++i)
#pragma unroll
                for (int j = 0; j < 4; ++j)
                    o[i][j] += p[i] * v[j];
        }
        __syncthreads();   // protects Ks/Ss/stats for next iteration
    }

    // epilogue: normalize and write merged-head layout
    float inv[4];
#pragma unroll
    for (int i = 0; i < 4; ++i) inv[i] = 1.0f / l_s[ty * 4 + i];
#pragma unroll
    for (int i = 0; i < 4; ++i) {
        float4 r;
        r.x = o[i][0] * inv[i];
        r.y = o[i][1] * inv[i];
        r.z = o[i][2] * inv[i];
        r.w = o[i][3] * inv[i];
        *(float4*)(ctx + (size_t)(q0 + ty * 4 + i) * D_MODEL + h * HDIM + tx * 4) = r;
    }
}

// ---------------------------------------------------------------------------
// kernel_launch
// Inputs (metadata order): q,k,v, Wq,bq, Wk,bk, Wv,bv, Wo,bo
// ---------------------------------------------------------------------------
extern "C" void kernel_launch(void* const* d_in, const int* in_sizes, int n_in,
                              void* d_out, int out_size)
{
    const float* q  = (const float*)d_in[0];
    const float* k  = (const float*)d_in[1];
    const float* v  = (const float*)d_in[2];
    const float* Wq = (const float*)d_in[3];
    const float* bq = (const float*)d_in[4];
    const float* Wk = (const float*)d_in[5];
    const float* bk = (const float*)d_in[6];
    const float* Wv = (const float*)d_in[7];
    const float* bv = (const float*)d_in[8];
    const float* Wo = (const float*)d_in[9];
    const float* bo = (const float*)d_in[10];
    float* out = (float*)d_out;

    float *qp, *kp, *vp, *ctx;
    cudaGetSymbolAddress((void**)&qp,  g_qp);
    cudaGetSymbolAddress((void**)&kp,  g_kp);
    cudaGetSymbolAddress((void**)&vp,  g_vp);
    cudaGetSymbolAddress((void**)&ctx, g_ctx);

    const int smem_flash = (3 * 64 * 65 + 3 * 64) * (int)sizeof(float);  // 50688 B
    cudaFuncSetAttribute(flash_attn_kernel,
                         cudaFuncAttributeMaxDynamicSharedMemorySize, smem_flash);

    dim3 gGemm(D_MODEL / 64, SEQ / 64);   // (12, 64)
    // Q/K/V projections
    gemm_bias_kernel<<<gGemm, 256>>>(q, Wq, bq, qp, SEQ, D_MODEL, D_MODEL);
    gemm_bias_kernel<<<gGemm, 256>>>(k, Wk, bk, kp, SEQ, D_MODEL, D_MODEL);
    gemm_bias_kernel<<<gGemm, 256>>>(v, Wv, bv, vp, SEQ, D_MODEL, D_MODEL);

    // attention
    dim3 gAttn(SEQ / 64, NHEAD);          // (64, 12)
    flash_attn_kernel<<<gAttn, 256, smem_flash>>>(qp, kp, vp, ctx);

    // output projection
    gemm_bias_kernel<<<gGemm, 256>>>(ctx, Wo, bo, out, SEQ, D_MODEL, D_MODEL);
}

// round 11
// speedup vs baseline: 2.3960x; 2.3960x over previous
#include <cuda_runtime.h>
#include <math.h>
#include <stdint.h>

#define D_MODEL 768
#define NHEAD   12
#define HDIM    64
#define SEQ     4096

// Scratch (allocation-free rule: __device__ globals)
__device__ float g_qp[SEQ * D_MODEL];
__device__ float g_kp[SEQ * D_MODEL];
__device__ float g_vp[SEQ * D_MODEL];
__device__ float g_ctx[SEQ * D_MODEL];

// ---------------------------------------------------------------------------
// helpers
// ---------------------------------------------------------------------------
__device__ __forceinline__ uint32_t f2tf(float x) {
    uint32_t r;
    asm("cvt.rna.tf32.f32 %0, %1;" : "=r"(r) : "f"(x));
    return r;
}

__device__ __forceinline__ void mma_tf32(float c[4],
                                         uint32_t a0, uint32_t a1, uint32_t a2, uint32_t a3,
                                         uint32_t b0, uint32_t b1) {
    asm volatile(
        "mma.sync.aligned.m16n8k8.row.col.f32.tf32.tf32.f32 "
        "{%0,%1,%2,%3}, {%4,%5,%6,%7}, {%8,%9}, {%0,%1,%2,%3};"
        : "+f"(c[0]), "+f"(c[1]), "+f"(c[2]), "+f"(c[3])
        : "r"(a0), "r"(a1), "r"(a2), "r"(a3), "r"(b0), "r"(b1));
}

__device__ __forceinline__ void store4_tf(float* d, float4 v) {
    d[0] = __uint_as_float(f2tf(v.x));
    d[1] = __uint_as_float(f2tf(v.y));
    d[2] = __uint_as_float(f2tf(v.z));
    d[3] = __uint_as_float(f2tf(v.w));
}

// ---------------------------------------------------------------------------
// tf32 GEMM: C[M,N] = X[M,K] @ W[N,K]^T + bias[N]
// CTA tile 128x64, BK=32, 256 threads, 8 warps (4m x 2n), warp tile 32x32.
// Smem stride 36 (== 4 mod 32) -> all fragment LDS conflict-free.
// ---------------------------------------------------------------------------
__global__ __launch_bounds__(256) void gemm_tf32_kernel(
    const float* __restrict__ X, const float* __restrict__ W,
    const float* __restrict__ bias, float* __restrict__ C,
    int M, int N, int K)
{
    __shared__ float As[128 * 36];
    __shared__ float Bs[64 * 36];

    const int t    = threadIdx.x;
    const int w    = t >> 5;
    const int lane = t & 31;
    const int gid  = lane >> 2;
    const int tig  = lane & 3;
    const int wm   = (w >> 1) * 32;   // warp row offset (0,32,64,96)
    const int wn   = (w & 1) * 32;    // warp col offset (0,32)
    const int m0   = blockIdx.y * 128;
    const int n0   = blockIdx.x * 64;

    float acc[2][4][4] = {};

    for (int kk = 0; kk < K; kk += 32) {
#pragma unroll
        for (int i = 0; i < 4; ++i) {           // A: 1024 float4
            int f = t + 256 * i;
            int r = f >> 3, c = (f & 7) * 4;
            float4 v = *(const float4*)(X + (size_t)(m0 + r) * K + kk + c);
            store4_tf(As + r * 36 + c, v);
        }
#pragma unroll
        for (int i = 0; i < 2; ++i) {           // B: 512 float4
            int f = t + 256 * i;
            int r = f >> 3, c = (f & 7) * 4;
            float4 v = *(const float4*)(W + (size_t)(n0 + r) * K + kk + c);
            store4_tf(Bs + r * 36 + c, v);
        }
        __syncthreads();

#pragma unroll
        for (int ks = 0; ks < 4; ++ks) {
            int kb = ks * 8;
            uint32_t a[2][4];
#pragma unroll
            for (int mi = 0; mi < 2; ++mi) {
                const float* p = As + (wm + mi * 16 + gid) * 36 + kb + tig;
                a[mi][0] = __float_as_uint(p[0]);
                a[mi][1] = __float_as_uint(p[8 * 36]);
                a[mi][2] = __float_as_uint(p[4]);
                a[mi][3] = __float_as_uint(p[8 * 36 + 4]);
            }
#pragma unroll
            for (int nj = 0; nj < 4; ++nj) {
                const float* p = Bs + (wn + nj * 8 + gid) * 36 + kb + tig;
                uint32_t b0 = __float_as_uint(p[0]);
                uint32_t b1 = __float_as_uint(p[4]);
#pragma unroll
                for (int mi = 0; mi < 2; ++mi)
                    mma_tf32(acc[mi][nj], a[mi][0], a[mi][1], a[mi][2], a[mi][3], b0, b1);
            }
        }
        __syncthreads();
    }

    // epilogue: bias + store (float2)
#pragma unroll
    for (int mi = 0; mi < 2; ++mi) {
#pragma unroll
        for (int nj = 0; nj < 4; ++nj) {
            int r = m0 + wm + mi * 16 + gid;
            int c = n0 + wn + nj * 8 + 2 * tig;
            float bx = bias[c], by = bias[c + 1];
            float2 r0 = make_float2(acc[mi][nj][0] + bx, acc[mi][nj][1] + by);
            float2 r1 = make_float2(acc[mi][nj][2] + bx, acc[mi][nj][3] + by);
            *(float2*)(C + (size_t)r * N + c)       = r0;
            *(float2*)(C + (size_t)(r + 8) * N + c) = r1;
        }
    }
}

// ---------------------------------------------------------------------------
// Flash attention with tf32 mma.
// Grid: (SEQ/128, NHEAD). Block: 256 threads (8 warps, 4m x 2n, 32x32 tiles).
// CTA: 128 query rows of one head, iterates 64-key tiles.
// Smem: Qs/Ss stride 68 (==4 mod 32), Vs stride 72 (==8 mod 32): all
// fragment LDS patterns are bank-conflict-free.
// ---------------------------------------------------------------------------
__global__ __launch_bounds__(256, 2) void flash_attn_tf32_kernel(
    const float* __restrict__ qp, const float* __restrict__ kp,
    const float* __restrict__ vp, float* __restrict__ ctx)
{
    extern __shared__ float sm[];
    float* Qs  = sm;                  // 128*68
    float* Ss  = Qs + 128 * 68;       // 128*68
    float* Ks  = Ss + 128 * 68;       // 64*68
    float* Vs  = Ks + 64 * 68;        // 64*72
    float* m_s = Vs + 64 * 72;        // 128
    float* l_s = m_s + 128;           // 128
    float* a_s = l_s + 128;           // 128

    const int h    = blockIdx.y;
    const int q0   = blockIdx.x * 128;
    const int t    = threadIdx.x;
    const int w    = t >> 5;
    const int lane = t & 31;
    const int gid  = lane >> 2;
    const int tig  = lane & 3;
    const int wm   = (w >> 1) * 32;
    const int wn   = (w & 1) * 32;
    const float scale = 0.125f;       // 1/sqrt(64)

    // Q tile: 128 rows x 64 dims = 2048 float4
#pragma unroll
    for (int i = 0; i < 8; ++i) {
        int f = t + 256 * i;
        int r = f >> 4, c = (f & 15) * 4;
        float4 v = *(const float4*)(qp + (size_t)(q0 + r) * D_MODEL + h * HDIM + c);
        store4_tf(Qs + r * 68 + c, v);
    }
    if (t < 128) { m_s[t] = -1e30f; l_s[t] = 0.0f; }

    float o[2][4][4] = {};
    __syncthreads();

    for (int k0 = 0; k0 < SEQ; k0 += 64) {
        // --- K tile
#pragma unroll
        for (int i = 0; i < 4; ++i) {
            int f = t + 256 * i;
            int r = f >> 4, c = (f & 15) * 4;
            float4 v = *(const float4*)(kp + (size_t)(k0 + r) * D_MODEL + h * HDIM + c);
            store4_tf(Ks + r * 68 + c, v);
        }
        __syncthreads();

        // --- S = Q @ K^T (128x64, k=64)
        float sacc[2][4][4] = {};
#pragma unroll
        for (int ks = 0; ks < 8; ++ks) {
            int kb = ks * 8;
            uint32_t a[2][4];
#pragma unroll
            for (int mi = 0; mi < 2; ++mi) {
                const float* p = Qs + (wm + mi * 16 + gid) * 68 + kb + tig;
                a[mi][0] = __float_as_uint(p[0]);
                a[mi][1] = __float_as_uint(p[8 * 68]);
                a[mi][2] = __float_as_uint(p[4]);
                a[mi][3] = __float_as_uint(p[8 * 68 + 4]);
            }
#pragma unroll
            for (int nj = 0; nj < 4; ++nj) {
                const float* p = Ks + (wn + nj * 8 + gid) * 68 + kb + tig;
                uint32_t b0 = __float_as_uint(p[0]);
                uint32_t b1 = __float_as_uint(p[4]);
#pragma unroll
                for (int mi = 0; mi < 2; ++mi)
                    mma_tf32(sacc[mi][nj], a[mi][0], a[mi][1], a[mi][2], a[mi][3], b0, b1);
            }
        }
        // store scaled S
#pragma unroll
        for (int mi = 0; mi < 2; ++mi) {
#pragma unroll
            for (int nj = 0; nj < 4; ++nj) {
                int r = wm + mi * 16 + gid;
                int c = wn + nj * 8 + 2 * tig;
                Ss[r * 68 + c]           = sacc[mi][nj][0] * scale;
                Ss[r * 68 + c + 1]       = sacc[mi][nj][1] * scale;
                Ss[(r + 8) * 68 + c]     = sacc[mi][nj][2] * scale;
                Ss[(r + 8) * 68 + c + 1] = sacc[mi][nj][3] * scale;
            }
        }
        // --- V tile (separate buffer; safe vs in-flight K reads)
#pragma unroll
        for (int i = 0; i < 4; ++i) {
            int f = t + 256 * i;
            int r = f >> 4, c = (f & 15) * 4;
            float4 v = *(const float4*)(vp + (size_t)(k0 + r) * D_MODEL + h * HDIM + c);
            store4_tf(Vs + r * 72 + c, v);
        }
        __syncthreads();

        // --- online softmax: 2 threads per row, 32 cols each
        {
            int row = t >> 1, half = t & 1;
            float* srow = Ss + row * 68 + half * 32;
            float mold = m_s[row];
            float lold = l_s[row];
            float pm = -1e30f;
#pragma unroll
            for (int j = 0; j < 32; ++j) pm = fmaxf(pm, srow[j]);
            pm = fmaxf(pm, __shfl_xor_sync(0xffffffffu, pm, 1));
            float mnew = fmaxf(mold, pm);
            float psum = 0.0f;
#pragma unroll
            for (int j = 0; j < 32; ++j) {
                float p = __expf(srow[j] - mnew);
                float pr = __uint_as_float(f2tf(p));   // round to tf32 (matches mma input)
                srow[j] = pr;
                psum += pr;
            }
            psum += __shfl_xor_sync(0xffffffffu, psum, 1);
            __syncwarp();
            if (half == 0) {
                float alpha = __expf(mold - mnew);
                l_s[row] = lold * alpha + psum;
                m_s[row] = mnew;
                a_s[row] = alpha;
            }
        }
        __syncthreads();

        // --- O = O*alpha + P @ V  (k = 64 keys)
        {
            float al0[2], al1[2];
#pragma unroll
            for (int mi = 0; mi < 2; ++mi) {
                al0[mi] = a_s[wm + mi * 16 + gid];
                al1[mi] = a_s[wm + mi * 16 + gid + 8];
            }
#pragma unroll
            for (int mi = 0; mi < 2; ++mi)
#pragma unroll
                for (int nj = 0; nj < 4; ++nj) {
                    o[mi][nj][0] *= al0[mi];
                    o[mi][nj][1] *= al0[mi];
                    o[mi][nj][2] *= al1[mi];
                    o[mi][nj][3] *= al1[mi];
                }
        }
#pragma unroll
        for (int ks = 0; ks < 8; ++ks) {
            int kb = ks * 8;
            uint32_t a[2][4];
#pragma unroll
            for (int mi = 0; mi < 2; ++mi) {
                const float* p = Ss + (wm + mi * 16 + gid) * 68 + kb + tig;
                a[mi][0] = __float_as_uint(p[0]);
                a[mi][1] = __float_as_uint(p[8 * 68]);
                a[mi][2] = __float_as_uint(p[4]);
                a[mi][3] = __float_as_uint(p[8 * 68 + 4]);
            }
#pragma unroll
            for (int nj = 0; nj < 4; ++nj) {
                int n = wn + nj * 8 + gid;
                uint32_t b0 = __float_as_uint(Vs[(kb + tig) * 72 + n]);
                uint32_t b1 = __float_as_uint(Vs[(kb + tig + 4) * 72 + n]);
#pragma unroll
                for (int mi = 0; mi < 2; ++mi)
                    mma_tf32(o[mi][nj], a[mi][0], a[mi][1], a[mi][2], a[mi][3], b0, b1);
            }
        }
        __syncthreads();   // protect Ss/Vs before next iteration
    }

    // epilogue: normalize, write merged-head layout
#pragma unroll
    for (int mi = 0; mi < 2; ++mi) {
        int r = wm + mi * 16 + gid;
        float inv0 = 1.0f / l_s[r];
        float inv1 = 1.0f / l_s[r + 8];
#pragma unroll
        for (int nj = 0; nj < 4; ++nj) {
            int c = h * HDIM + wn + nj * 8 + 2 * tig;
            float2 r0 = make_float2(o[mi][nj][0] * inv0, o[mi][nj][1] * inv0);
            float2 r1 = make_float2(o[mi][nj][2] * inv1, o[mi][nj][3] * inv1);
            *(float2*)(ctx + (size_t)(q0 + r) * D_MODEL + c)     = r0;
            *(float2*)(ctx + (size_t)(q0 + r + 8) * D_MODEL + c) = r1;
        }
    }
}

// ---------------------------------------------------------------------------
// kernel_launch  (inputs: q,k,v, Wq,bq, Wk,bk, Wv,bv, Wo,bo)
// ---------------------------------------------------------------------------
extern "C" void kernel_launch(void* const* d_in, const int* in_sizes, int n_in,
                              void* d_out, int out_size)
{
    const float* q  = (const float*)d_in[0];
    const float* k  = (const float*)d_in[1];
    const float* v  = (const float*)d_in[2];
    const float* Wq = (const float*)d_in[3];
    const float* bq = (const float*)d_in[4];
    const float* Wk = (const float*)d_in[5];
    const float* bk = (const float*)d_in[6];
    const float* Wv = (const float*)d_in[7];
    const float* bv = (const float*)d_in[8];
    const float* Wo = (const float*)d_in[9];
    const float* bo = (const float*)d_in[10];
    float* out = (float*)d_out;

    float *qp, *kp, *vp, *ctx;
    cudaGetSymbolAddress((void**)&qp,  g_qp);
    cudaGetSymbolAddress((void**)&kp,  g_kp);
    cudaGetSymbolAddress((void**)&vp,  g_vp);
    cudaGetSymbolAddress((void**)&ctx, g_ctx);

    const int smem_attn = (2 * 128 * 68 + 64 * 68 + 64 * 72 + 3 * 128) * (int)sizeof(float);
    cudaFuncSetAttribute(flash_attn_tf32_kernel,
                         cudaFuncAttributeMaxDynamicSharedMemorySize, smem_attn);

    dim3 gGemm(D_MODEL / 64, SEQ / 128);   // (12, 32)
    gemm_tf32_kernel<<<gGemm, 256>>>(q, Wq, bq, qp, SEQ, D_MODEL, D_MODEL);
    gemm_tf32_kernel<<<gGemm, 256>>>(k, Wk, bk, kp, SEQ, D_MODEL, D_MODEL);
    gemm_tf32_kernel<<<gGemm, 256>>>(v, Wv, bv, vp, SEQ, D_MODEL, D_MODEL);

    dim3 gAttn(SEQ / 128, NHEAD);          // (32, 12)
    flash_attn_tf32_kernel<<<gAttn, 256, smem_attn>>>(qp, kp, vp, ctx);

    gemm_tf32_kernel<<<gGemm, 256>>>(ctx, Wo, bo, out, SEQ, D_MODEL, D_MODEL);
}

// round 13
// speedup vs baseline: 3.8666x; 1.6137x over previous
#include <cuda_runtime.h>
#include <math.h>
#include <stdint.h>

#define D_MODEL 768
#define NHEAD   12
#define HDIM    64
#define SEQ     4096

// Scratch (allocation-free rule: __device__ globals)
__device__ float g_qp[SEQ * D_MODEL];
__device__ float g_kp[SEQ * D_MODEL];
__device__ float g_vp[SEQ * D_MODEL];
__device__ float g_ctx[SEQ * D_MODEL];

// ---------------------------------------------------------------------------
// helpers
// ---------------------------------------------------------------------------
__device__ __forceinline__ uint32_t f2tf(float x) {
    uint32_t r;
    asm("cvt.rna.tf32.f32 %0, %1;" : "=r"(r) : "f"(x));
    return r;
}

__device__ __forceinline__ void mma_tf32(float c[4],
                                         uint32_t a0, uint32_t a1, uint32_t a2, uint32_t a3,
                                         uint32_t b0, uint32_t b1) {
    asm volatile(
        "mma.sync.aligned.m16n8k8.row.col.f32.tf32.tf32.f32 "
        "{%0,%1,%2,%3}, {%4,%5,%6,%7}, {%8,%9}, {%0,%1,%2,%3};"
        : "+f"(c[0]), "+f"(c[1]), "+f"(c[2]), "+f"(c[3])
        : "r"(a0), "r"(a1), "r"(a2), "r"(a3), "r"(b0), "r"(b1));
}

__device__ __forceinline__ void store4_tf(float* d, float4 v) {
    d[0] = __uint_as_float(f2tf(v.x));
    d[1] = __uint_as_float(f2tf(v.y));
    d[2] = __uint_as_float(f2tf(v.z));
    d[3] = __uint_as_float(f2tf(v.w));
}

// ---------------------------------------------------------------------------
// Shared tf32 GEMM body: C[M,N] = X[M,K] @ W[N,K]^T + bias[N]
// CTA tile 128x64, BK=32, 256 threads, 8 warps (4m x 2n), warp tile 32x32.
// Smem stride 36 (== 4 mod 32) -> all fragment LDS conflict-free.
// Register-prefetch of the next A/B tiles hides global-load latency.
// ---------------------------------------------------------------------------
__device__ __forceinline__ void gemm_body(
    const float* __restrict__ X, const float* __restrict__ W,
    const float* __restrict__ bias, float* __restrict__ C,
    int M, int N, int K, float* As, float* Bs)
{
    const int t    = threadIdx.x;
    const int w    = t >> 5;
    const int lane = t & 31;
    const int gid  = lane >> 2;
    const int tig  = lane & 3;
    const int wm   = (w >> 1) * 32;
    const int wn   = (w & 1) * 32;
    const int m0   = blockIdx.y * 128;
    const int n0   = blockIdx.x * 64;

    const int lrA = t >> 3, lcA = (t & 7) * 4;   // A/B load coords (row step 32 per i)

    float acc[2][4][4] = {};
    float4 pa[4], pb[2];

    // preload tile kk=0
#pragma unroll
    for (int i = 0; i < 4; ++i)
        pa[i] = *(const float4*)(X + (size_t)(m0 + lrA + 32 * i) * K + lcA);
#pragma unroll
    for (int i = 0; i < 2; ++i)
        pb[i] = *(const float4*)(W + (size_t)(n0 + lrA + 32 * i) * K + lcA);

    for (int kk = 0; kk < K; kk += 32) {
        // store prefetched regs to smem (with tf32 rounding)
#pragma unroll
        for (int i = 0; i < 4; ++i)
            store4_tf(As + (lrA + 32 * i) * 36 + lcA, pa[i]);
#pragma unroll
        for (int i = 0; i < 2; ++i)
            store4_tf(Bs + (lrA + 32 * i) * 36 + lcA, pb[i]);
        __syncthreads();

        // issue prefetch of next tile (latency hidden behind mma phase)
        int nk = (kk + 32 < K) ? kk + 32 : 0;
#pragma unroll
        for (int i = 0; i < 4; ++i)
            pa[i] = *(const float4*)(X + (size_t)(m0 + lrA + 32 * i) * K + nk + lcA);
#pragma unroll
        for (int i = 0; i < 2; ++i)
            pb[i] = *(const float4*)(W + (size_t)(n0 + lrA + 32 * i) * K + nk + lcA);

#pragma unroll
        for (int ks = 0; ks < 4; ++ks) {
            int kb = ks * 8;
            uint32_t a[2][4];
#pragma unroll
            for (int mi = 0; mi < 2; ++mi) {
                const float* p = As + (wm + mi * 16 + gid) * 36 + kb + tig;
                a[mi][0] = __float_as_uint(p[0]);
                a[mi][1] = __float_as_uint(p[8 * 36]);
                a[mi][2] = __float_as_uint(p[4]);
                a[mi][3] = __float_as_uint(p[8 * 36 + 4]);
            }
#pragma unroll
            for (int nj = 0; nj < 4; ++nj) {
                const float* p = Bs + (wn + nj * 8 + gid) * 36 + kb + tig;
                uint32_t b0 = __float_as_uint(p[0]);
                uint32_t b1 = __float_as_uint(p[4]);
#pragma unroll
                for (int mi = 0; mi < 2; ++mi)
                    mma_tf32(acc[mi][nj], a[mi][0], a[mi][1], a[mi][2], a[mi][3], b0, b1);
            }
        }
        __syncthreads();
    }

    // epilogue: bias + store (float2)
#pragma unroll
    for (int mi = 0; mi < 2; ++mi) {
#pragma unroll
        for (int nj = 0; nj < 4; ++nj) {
            int r = m0 + wm + mi * 16 + gid;
            int c = n0 + wn + nj * 8 + 2 * tig;
            float bx = bias[c], by = bias[c + 1];
            float2 r0 = make_float2(acc[mi][nj][0] + bx, acc[mi][nj][1] + by);
            float2 r1 = make_float2(acc[mi][nj][2] + bx, acc[mi][nj][3] + by);
            *(float2*)(C + (size_t)r * N + c)       = r0;
            *(float2*)(C + (size_t)(r + 8) * N + c) = r1;
        }
    }
}

// single GEMM (output projection)
__global__ __launch_bounds__(256) void gemm_tf32_kernel(
    const float* __restrict__ X, const float* __restrict__ W,
    const float* __restrict__ bias, float* __restrict__ C,
    int M, int N, int K)
{
    __shared__ float As[128 * 36];
    __shared__ float Bs[64 * 36];
    gemm_body(X, W, bias, C, M, N, K, As, Bs);
}

// fused Q/K/V projections: blockIdx.z selects which projection
__global__ __launch_bounds__(256) void gemm_qkv_kernel(
    const float* __restrict__ q, const float* __restrict__ k, const float* __restrict__ v,
    const float* __restrict__ Wq, const float* __restrict__ bq,
    const float* __restrict__ Wk, const float* __restrict__ bk,
    const float* __restrict__ Wv, const float* __restrict__ bv,
    float* __restrict__ qp, float* __restrict__ kp, float* __restrict__ vp)
{
    __shared__ float As[128 * 36];
    __shared__ float Bs[64 * 36];
    const float* X; const float* W; const float* B; float* C;
    if (blockIdx.z == 0)      { X = q; W = Wq; B = bq; C = qp; }
    else if (blockIdx.z == 1) { X = k; W = Wk; B = bk; C = kp; }
    else                      { X = v; W = Wv; B = bv; C = vp; }
    gemm_body(X, W, B, C, SEQ, D_MODEL, D_MODEL, As, Bs);
}

// ---------------------------------------------------------------------------
// Flash attention with tf32 mma, software-pipelined K tile.
// Grid: (SEQ/128, NHEAD). Block: 256 threads (8 warps, 4m x 2n, 32x32 tiles).
// Per iteration: 3 syncs (was 4); K_{i+1} global load issued right after the
// QK mma and consumed at the next loop top (latency hidden behind softmax+PV).
// V load is issued before the softmax barrier and consumed after it (hidden).
// Numerics identical to the R11 passing kernel (same op order everywhere).
// ---------------------------------------------------------------------------
__global__ __launch_bounds__(256, 2) void flash_attn_tf32_kernel(
    const float* __restrict__ qp, const float* __restrict__ kp,
    const float* __restrict__ vp, float* __restrict__ ctx)
{
    extern __shared__ float sm[];
    float* Qs  = sm;                  // 128*68
    float* Ss  = Qs + 128 * 68;       // 128*68
    float* Ks  = Ss + 128 * 68;       // 64*68
    float* Vs  = Ks + 64 * 68;        // 64*72
    float* m_s = Vs + 64 * 72;        // 128
    float* l_s = m_s + 128;           // 128
    float* a_s = l_s + 128;           // 128

    const int h    = blockIdx.y;
    const int q0   = blockIdx.x * 128;
    const int t    = threadIdx.x;
    const int w    = t >> 5;
    const int lane = t & 31;
    const int gid  = lane >> 2;
    const int tig  = lane & 3;
    const int wm   = (w >> 1) * 32;
    const int wn   = (w & 1) * 32;
    const float scale = 0.125f;       // 1/sqrt(64)

    const int lrT = t >> 4;            // K/V tile load coords: row step 16 per i
    const int lcT = (t & 15) * 4;

    // Q tile: 128 rows x 64 dims
#pragma unroll
    for (int i = 0; i < 8; ++i) {
        int r = lrT + 16 * i;
        float4 v = *(const float4*)(qp + (size_t)(q0 + r) * D_MODEL + h * HDIM + lcT);
        store4_tf(Qs + r * 68 + lcT, v);
    }
    if (t < 128) { m_s[t] = -1e30f; l_s[t] = 0.0f; }

    // preload K tile 0 into registers
    float4 kreg[4];
#pragma unroll
    for (int i = 0; i < 4; ++i)
        kreg[i] = *(const float4*)(kp + (size_t)(lrT + 16 * i) * D_MODEL + h * HDIM + lcT);

    float o[2][4][4] = {};

    for (int k0 = 0; k0 < SEQ; k0 += 64) {
        // store prefetched K regs -> Ks (prev QK reads of Ks are behind last sync)
#pragma unroll
        for (int i = 0; i < 4; ++i)
            store4_tf(Ks + (lrT + 16 * i) * 68 + lcT, kreg[i]);
        __syncthreads();              // TOP: Ks (and first-iter Qs/stats) visible

        // --- S = Q @ K^T (128x64, k=64)
        float sacc[2][4][4] = {};
#pragma unroll
        for (int ks = 0; ks < 8; ++ks) {
            int kb = ks * 8;
            uint32_t a[2][4];
#pragma unroll
            for (int mi = 0; mi < 2; ++mi) {
                const float* p = Qs + (wm + mi * 16 + gid) * 68 + kb + tig;
                a[mi][0] = __float_as_uint(p[0]);
                a[mi][1] = __float_as_uint(p[8 * 68]);
                a[mi][2] = __float_as_uint(p[4]);
                a[mi][3] = __float_as_uint(p[8 * 68 + 4]);
            }
#pragma unroll
            for (int nj = 0; nj < 4; ++nj) {
                const float* p = Ks + (wn + nj * 8 + gid) * 68 + kb + tig;
                uint32_t b0 = __float_as_uint(p[0]);
                uint32_t b1 = __float_as_uint(p[4]);
#pragma unroll
                for (int mi = 0; mi < 2; ++mi)
                    mma_tf32(sacc[mi][nj], a[mi][0], a[mi][1], a[mi][2], a[mi][3], b0, b1);
            }
        }

        // issue prefetch of next K tile (consumed at next loop top)
        {
            int nk0 = (k0 + 64 < SEQ) ? k0 + 64 : 0;
#pragma unroll
            for (int i = 0; i < 4; ++i)
                kreg[i] = *(const float4*)(kp + (size_t)(nk0 + lrT + 16 * i) * D_MODEL + h * HDIM + lcT);
        }

        // store scaled S (float2 pairs)
#pragma unroll
        for (int mi = 0; mi < 2; ++mi) {
#pragma unroll
            for (int nj = 0; nj < 4; ++nj) {
                int r = wm + mi * 16 + gid;
                int c = wn + nj * 8 + 2 * tig;
                *(float2*)(Ss + r * 68 + c) =
                    make_float2(sacc[mi][nj][0] * scale, sacc[mi][nj][1] * scale);
                *(float2*)(Ss + (r + 8) * 68 + c) =
                    make_float2(sacc[mi][nj][2] * scale, sacc[mi][nj][3] * scale);
            }
        }

        // V tile -> Vs (issued before sync A, consumed after sync B: hidden)
#pragma unroll
        for (int i = 0; i < 4; ++i) {
            int r = lrT + 16 * i;
            float4 v = *(const float4*)(vp + (size_t)(k0 + r) * D_MODEL + h * HDIM + lcT);
            store4_tf(Vs + r * 72 + lcT, v);
        }
        __syncthreads();              // A: Ss complete (Vs guaranteed by B)

        // --- online softmax: 2 threads per row, 32 cols each (float4 passes)
        {
            int row = t >> 1, half = t & 1;
            float* srow = Ss + row * 68 + half * 32;
            float mold = m_s[row];
            float lold = l_s[row];
            float pm = -1e30f;
#pragma unroll
            for (int j = 0; j < 8; ++j) {
                float4 sv = *(const float4*)(srow + 4 * j);
                pm = fmaxf(pm, fmaxf(fmaxf(sv.x, sv.y), fmaxf(sv.z, sv.w)));
            }
            pm = fmaxf(pm, __shfl_xor_sync(0xffffffffu, pm, 1));
            float mnew = fmaxf(mold, pm);
            float psum = 0.0f;
#pragma unroll
            for (int j = 0; j < 8; ++j) {
                float4 sv = *(float4*)(srow + 4 * j);
                sv.x = __uint_as_float(f2tf(__expf(sv.x - mnew))); psum += sv.x;
                sv.y = __uint_as_float(f2tf(__expf(sv.y - mnew))); psum += sv.y;
                sv.z = __uint_as_float(f2tf(__expf(sv.z - mnew))); psum += sv.z;
                sv.w = __uint_as_float(f2tf(__expf(sv.w - mnew))); psum += sv.w;
                *(float4*)(srow + 4 * j) = sv;
            }
            psum += __shfl_xor_sync(0xffffffffu, psum, 1);
            __syncwarp();
            if (half == 0) {
                float alpha = __expf(mold - mnew);
                l_s[row] = lold * alpha + psum;
                m_s[row] = mnew;
                a_s[row] = alpha;
            }
        }
        __syncthreads();              // B: P final, stats ready, Vs visible

        // --- O = O*alpha + P @ V  (k = 64 keys)
        {
            float al0[2], al1[2];
#pragma unroll
            for (int mi = 0; mi < 2; ++mi) {
                al0[mi] = a_s[wm + mi * 16 + gid];
                al1[mi] = a_s[wm + mi * 16 + gid + 8];
            }
#pragma unroll
            for (int mi = 0; mi < 2; ++mi)
#pragma unroll
                for (int nj = 0; nj < 4; ++nj) {
                    o[mi][nj][0] *= al0[mi];
                    o[mi][nj][1] *= al0[mi];
                    o[mi][nj][2] *= al1[mi];
                    o[mi][nj][3] *= al1[mi];
                }
        }
#pragma unroll
        for (int ks = 0; ks < 8; ++ks) {
            int kb = ks * 8;
            uint32_t a[2][4];
#pragma unroll
            for (int mi = 0; mi < 2; ++mi) {
                const float* p = Ss + (wm + mi * 16 + gid) * 68 + kb + tig;
                a[mi][0] = __float_as_uint(p[0]);
                a[mi][1] = __float_as_uint(p[8 * 68]);
                a[mi][2] = __float_as_uint(p[4]);
                a[mi][3] = __float_as_uint(p[8 * 68 + 4]);
            }
#pragma unroll
            for (int nj = 0; nj < 4; ++nj) {
                int n = wn + nj * 8 + gid;
                uint32_t b0 = __float_as_uint(Vs[(kb + tig) * 72 + n]);
                uint32_t b1 = __float_as_uint(Vs[(kb + tig + 4) * 72 + n]);
#pragma unroll
                for (int mi = 0; mi < 2; ++mi)
                    mma_tf32(o[mi][nj], a[mi][0], a[mi][1], a[mi][2], a[mi][3], b0, b1);
            }
        }
        // no sync here: next-iter Ks store is WAR-safe (QK long done), and the
        // TOP sync orders it before any reader; Ss/Vs writes of iter i+1 happen
        // after TOP sync, which follows this PV.
    }

    // epilogue: normalize, write merged-head layout (l_s final since sync B)
#pragma unroll
    for (int mi = 0; mi < 2; ++mi) {
        int r = wm + mi * 16 + gid;
        float inv0 = 1.0f / l_s[r];
        float inv1 = 1.0f / l_s[r + 8];
#pragma unroll
        for (int nj = 0; nj < 4; ++nj) {
            int c = h * HDIM + wn + nj * 8 + 2 * tig;
            float2 r0 = make_float2(o[mi][nj][0] * inv0, o[mi][nj][1] * inv0);
            float2 r1 = make_float2(o[mi][nj][2] * inv1, o[mi][nj][3] * inv1);
            *(float2*)(ctx + (size_t)(q0 + r) * D_MODEL + c)     = r0;
            *(float2*)(ctx + (size_t)(q0 + r + 8) * D_MODEL + c) = r1;
        }
    }
}

// ---------------------------------------------------------------------------
// kernel_launch  (inputs: q,k,v, Wq,bq, Wk,bk, Wv,bv, Wo,bo)
// ---------------------------------------------------------------------------
extern "C" void kernel_launch(void* const* d_in, const int* in_sizes, int n_in,
                              void* d_out, int out_size)
{
    const float* q  = (const float*)d_in[0];
    const float* k  = (const float*)d_in[1];
    const float* v  = (const float*)d_in[2];
    const float* Wq = (const float*)d_in[3];
    const float* bq = (const float*)d_in[4];
    const float* Wk = (const float*)d_in[5];
    const float* bk = (const float*)d_in[6];
    const float* Wv = (const float*)d_in[7];
    const float* bv = (const float*)d_in[8];
    const float* Wo = (const float*)d_in[9];
    const float* bo = (const float*)d_in[10];
    float* out = (float*)d_out;

    float *qp, *kp, *vp, *ctx;
    cudaGetSymbolAddress((void**)&qp,  g_qp);
    cudaGetSymbolAddress((void**)&kp,  g_kp);
    cudaGetSymbolAddress((void**)&vp,  g_vp);
    cudaGetSymbolAddress((void**)&ctx, g_ctx);

    const int smem_attn = (2 * 128 * 68 + 64 * 68 + 64 * 72 + 3 * 128) * (int)sizeof(float);
    cudaFuncSetAttribute(flash_attn_tf32_kernel,
                         cudaFuncAttributeMaxDynamicSharedMemorySize, smem_attn);

    // fused Q/K/V projections (one launch, 3.9 waves instead of 3 x 1.3)
    dim3 gQKV(D_MODEL / 64, SEQ / 128, 3);
    gemm_qkv_kernel<<<gQKV, 256>>>(q, k, v, Wq, bq, Wk, bk, Wv, bv, qp, kp, vp);

    // attention
    dim3 gAttn(SEQ / 128, NHEAD);          // (32, 12)
    flash_attn_tf32_kernel<<<gAttn, 256, smem_attn>>>(qp, kp, vp, ctx);

    // output projection
    dim3 gGemm(D_MODEL / 64, SEQ / 128);   // (12, 32)
    gemm_tf32_kernel<<<gGemm, 256>>>(ctx, Wo, bo, out, SEQ, D_MODEL, D_MODEL);
}